// round 7
// baseline (speedup 1.0000x reference)
#include <cuda_runtime.h>
#include <cstdint>
#include <cstddef>

#define NE 8
#define TOPK 2
#define TT 4096
#define HH 2048
#define FF 8192
#define BM 128
#define MAXROWS (TT * TOPK + NE * BM)            /* 9216 padded pair rows */
#define MAXTILES ((TT * TOPK) / BM + NE)         /* 72 */

/* fragment-major smem geometry (words = 4B) */
#define TSA 132                                  /* A tile: 128 + 4 pad   */
#define TSB 68                                   /* B tile: 64 + 4 pad    */
#define A_WORDS (32 * TSA)                       /* 8 tr x 4 tk tiles     */
#define B_WORDS (64 * TSB)                       /* 16 nt x 4 tk tiles    */
#define STAGE_BYTES ((A_WORDS + B_WORDS) * 4)    /* 34304                 */
#define GEMM_SMEM (2 * STAGE_BYTES)              /* 68608                 */

/* ------------------------------ scratch ------------------------------ */
__device__ float g_hact[(size_t)MAXROWS * FF];
__device__ float g_y[(size_t)MAXROWS * HH];
__device__ int   g_counts[NE];
__device__ int   g_base[NE];
__device__ int   g_tileE[MAXTILES];
__device__ int   g_tilePr0[MAXTILES];
__device__ int   g_ntiles;
__device__ int   g_tok[MAXROWS];
__device__ int   g_te[TT * TOPK];
__device__ float g_twt[TT * TOPK];
__device__ int   g_tpos[TT * TOPK];
__device__ int   g_trow[TT * TOPK];

/* ------------------------------ helpers ------------------------------ */
__device__ __forceinline__ uint32_t f2tf32(float x) {
    uint32_t u;
    asm("cvt.rna.tf32.f32 %0, %1;" : "=r"(u) : "f"(x));
    return u;
}

__device__ __forceinline__ uint32_t smem_u32(const void* p) {
    uint32_t a;
    asm("{ .reg .u64 t; cvta.to.shared.u64 t, %1; cvt.u32.u64 %0, t; }"
        : "=r"(a) : "l"(p));
    return a;
}

__device__ __forceinline__ void sts32(uint32_t a, uint32_t v) {
    asm volatile("st.shared.b32 [%0], %1;" :: "r"(a), "r"(v) : "memory");
}

__device__ __forceinline__ uint4 lds128(uint32_t a) {
    uint4 r;
    asm volatile("ld.shared.v4.b32 {%0,%1,%2,%3}, [%4];"
                 : "=r"(r.x), "=r"(r.y), "=r"(r.z), "=r"(r.w) : "r"(a));
    return r;
}

__device__ __forceinline__ uint2 lds64(uint32_t a) {
    uint2 r;
    asm volatile("ld.shared.v2.b32 {%0,%1}, [%2];"
                 : "=r"(r.x), "=r"(r.y) : "r"(a));
    return r;
}

__device__ __forceinline__ void mma8(float* d, const uint32_t* a,
                                     uint32_t b0, uint32_t b1) {
    asm volatile(
        "mma.sync.aligned.m16n8k8.row.col.f32.tf32.tf32.f32 "
        "{%0,%1,%2,%3}, {%4,%5,%6,%7}, {%8,%9}, {%0,%1,%2,%3};\n"
        : "+f"(d[0]), "+f"(d[1]), "+f"(d[2]), "+f"(d[3])
        : "r"(a[0]), "r"(a[1]), "r"(a[2]), "r"(a[3]), "r"(b0), "r"(b1));
}

/* ------------------------- routing kernels --------------------------- */
__global__ void zero_kernel() {
    if (threadIdx.x < NE) g_counts[threadIdx.x] = 0;
}

__global__ __launch_bounds__(128)
void router_kernel(const float* __restrict__ hs, const float* __restrict__ gw) {
    __shared__ float Xs[128][33];
    __shared__ float Gs[8][33];
    const int tid = threadIdx.x;
    const int tok0 = blockIdx.x * 128;

    float acc[NE];
#pragma unroll
    for (int e = 0; e < NE; e++) acc[e] = 0.f;

    for (int kc = 0; kc < HH; kc += 32) {
#pragma unroll
        for (int j = 0; j < 8; j++) {
            int idx = j * 128 + tid;
            int r = idx >> 3;
            int c4 = (idx & 7) * 4;
            float4 v = *(const float4*)&hs[(size_t)(tok0 + r) * HH + kc + c4];
            Xs[r][c4 + 0] = v.x; Xs[r][c4 + 1] = v.y;
            Xs[r][c4 + 2] = v.z; Xs[r][c4 + 3] = v.w;
        }
        if (tid < 64) {
            int r = tid >> 3;
            int c4 = (tid & 7) * 4;
            float4 v = *(const float4*)&gw[(size_t)r * HH + kc + c4];
            Gs[r][c4 + 0] = v.x; Gs[r][c4 + 1] = v.y;
            Gs[r][c4 + 2] = v.z; Gs[r][c4 + 3] = v.w;
        }
        __syncthreads();
#pragma unroll
        for (int c = 0; c < 32; c++) {
            float x = Xs[tid][c];
#pragma unroll
            for (int e = 0; e < NE; e++) acc[e] += x * Gs[e][c];
        }
        __syncthreads();
    }

    float mx = acc[0];
#pragma unroll
    for (int e = 1; e < NE; e++) mx = fmaxf(mx, acc[e]);
    float p[NE];
#pragma unroll
    for (int e = 0; e < NE; e++) p[e] = expf(acc[e] - mx);

    int i1 = 0;
#pragma unroll
    for (int e = 1; e < NE; e++) if (p[e] > p[i1]) i1 = e;
    int i2 = (i1 == 0) ? 1 : 0;
#pragma unroll
    for (int e = 0; e < NE; e++) if (e != i1 && p[e] > p[i2]) i2 = e;

    float wa = p[i1], wb = p[i2];
    float inv = 1.f / (wa + wb);
    int t = tok0 + tid;
    int pos0 = atomicAdd(&g_counts[i1], 1);
    int pos1 = atomicAdd(&g_counts[i2], 1);
    g_te[t * 2 + 0] = i1; g_twt[t * 2 + 0] = wa * inv; g_tpos[t * 2 + 0] = pos0;
    g_te[t * 2 + 1] = i2; g_twt[t * 2 + 1] = wb * inv; g_tpos[t * 2 + 1] = pos1;
}

__global__ void scan_kernel() {
    if (threadIdx.x != 0) return;
    int b = 0, t = 0;
    for (int e = 0; e < NE; e++) {
        int cnt = g_counts[e];
        g_base[e] = b;
        int tiles = (cnt + BM - 1) / BM;
        for (int i = 0; i < tiles; i++) {
            g_tileE[t] = e;
            g_tilePr0[t] = b + i * BM;
            t++;
        }
        b += tiles * BM;
    }
    g_ntiles = t;
}

__global__ void build_kernel() {
    int t = blockIdx.x * blockDim.x + threadIdx.x;
    if (t >= TT) return;
#pragma unroll
    for (int s = 0; s < 2; s++) {
        int e = g_te[t * 2 + s];
        int row = g_base[e] + g_tpos[t * 2 + s];
        g_tok[row] = t;
        g_trow[t * 2 + s] = row;
    }
}

/* ----------------- shared producer/consumer machinery ----------------
   A: 128 rows x 32 k per stage, fragment-major:
     tile (tr = row>>4, tk = k>>3), lane_c = (row&7)*4 + (k&3),
     reg = ((k>>2)&1)*2 + ((row>>3)&1), slot = lane_c ^ ((lane_c>>3)&3)
     word = (tr*4+tk)*TSA + slot*4 + reg
   B: 128 rows x 32 k, tiles of 8n x 8k:
     reg = (k>>2)&1, word = A_WORDS + ((n>>3)*4+tk)*TSB + slot*2 + reg  */

#define PRODUCER_SETUP(prow)                                               \
    const int kh = (tid & 1) * 16;                                         \
    const int sw = ((prow) & 7) >> 1;                                      \
    uint32_t aw[4], bw[4];                                                 \
    _Pragma("unroll")                                                      \
    for (int q = 0; q < 4; q++) {                                          \
        int tk = ((tid & 1) << 1) + (q >> 1);                              \
        aw[q] = sb + 4u * ((((prow) >> 4) * 4 + tk) * TSA +                \
                           ((prow) & 7) * 16 + ((q & 1) << 1) +            \
                           (((prow) >> 3) & 1));                           \
        bw[q] = sb + 4u * (A_WORDS + (((prow) >> 3) * 4 + tk) * TSB +      \
                           ((prow) & 7) * 8 + (q & 1));                    \
    }

#define LOADV(s)                                                           \
    _Pragma("unroll")                                                      \
    for (int q = 0; q < 4; q++) {                                          \
        vA[q] = *(const float4*)(ap + (size_t)(s) * 32 + 4 * q);           \
        vB[q] = *(const float4*)(bp + (size_t)(s) * 32 + 4 * q);           \
    }

#define STOREV(buf)                                                       \
    {                                                                     \
        uint32_t o = (buf) * STAGE_BYTES;                                 \
        _Pragma("unroll")                                                 \
        for (int q = 0; q < 4; q++) {                                     \
            sts32(aw[q] + o + ((0 ^ sw) << 4), f2tf32(vA[q].x));          \
            sts32(aw[q] + o + ((1 ^ sw) << 4), f2tf32(vA[q].y));          \
            sts32(aw[q] + o + ((2 ^ sw) << 4), f2tf32(vA[q].z));          \
            sts32(aw[q] + o + ((3 ^ sw) << 4), f2tf32(vA[q].w));          \
            sts32(bw[q] + o + ((0 ^ sw) << 3), f2tf32(vB[q].x));          \
            sts32(bw[q] + o + ((1 ^ sw) << 3), f2tf32(vB[q].y));          \
            sts32(bw[q] + o + ((2 ^ sw) << 3), f2tf32(vB[q].z));          \
            sts32(bw[q] + o + ((3 ^ sw) << 3), f2tf32(vB[q].w));          \
        }                                                                 \
    }

/* consumer: per tk, 2 A frags (LDS.128) + 8 B frags (LDS.64) + 16 MMA */
#define COMPUTE(buf, NTILE_EXPR)                                          \
    {                                                                     \
        uint32_t so = (buf) * STAGE_BYTES;                                \
        _Pragma("unroll")                                                 \
        for (int tk = 0; tk < 4; tk++) {                                  \
            uint4 a0 = lds128(aoff + so + (tr0 * 4 + tk) * (TSA * 4));    \
            uint4 a1 = lds128(aoff + so + ((tr0 + 1) * 4 + tk) * (TSA * 4)); \
            _Pragma("unroll")                                             \
            for (int nt = 0; nt < 8; nt++) {                              \
                int ntile = (NTILE_EXPR);                                 \
                uint2 b = lds64(boff + so + (ntile * 4 + tk) * (TSB * 4)); \
                mma8(acc[0][nt], (const uint32_t*)&a0, b.x, b.y);         \
                mma8(acc[1][nt], (const uint32_t*)&a1, b.x, b.y);         \
            }                                                             \
        }                                                                 \
    }

/* ------------------------------- GEMM1 -------------------------------
   g_hact[row, n0..n0+63] = silu(X w1^T) * (X w3^T), per-tile expert.
   B rows 0-63 = w1 slice, 64-127 = w3 slice. NS = 2048/32 = 64.        */
__global__ __launch_bounds__(256)
void gemm1_k(const float* __restrict__ hs, const float* __restrict__ w1g,
             const float* __restrict__ w3g) {
    extern __shared__ float smem[];
    const uint32_t sb = smem_u32(smem);
    const int tile = blockIdx.x;
    if (tile >= g_ntiles) return;
    const int e = g_tileE[tile];
    const int pr0 = g_tilePr0[tile];
    const int n0 = blockIdx.y * 64;

    const int tid = threadIdx.x;
    const int lane = tid & 31;
    const int w = tid >> 5;

    /* producer */
    const int prow = tid >> 1;
    PRODUCER_SETUP(prow);
    int tok = g_tok[pr0 + prow];
    tok = min(max(tok, 0), TT - 1);
    const float* ap = hs + (size_t)tok * HH + kh;
    const float* bp = (prow < 64)
        ? w1g + ((size_t)e * FF + n0 + prow) * HH + kh
        : w3g + ((size_t)e * FF + n0 + prow - 64) * HH + kh;

    /* consumer */
    const int wm = (w & 3) * 32;
    const int h = w >> 2;
    const int tr0 = (w & 3) * 2;
    const int slotL = lane ^ ((lane >> 3) & 3);
    const uint32_t aoff = sb + slotL * 16;
    const uint32_t boff = sb + A_WORDS * 4 + slotL * 8;

    float acc[2][8][4];
#pragma unroll
    for (int m = 0; m < 2; m++)
#pragma unroll
        for (int n = 0; n < 8; n++)
#pragma unroll
            for (int i = 0; i < 4; i++) acc[m][n][i] = 0.f;

    float4 vA[4], vB[4];
    LOADV(0);
    STOREV(0);
    __syncthreads();

    const int NS = HH / 32;  /* 64 */
    for (int s = 0; s < NS; s++) {
        const int buf = s & 1;
        if (s + 1 < NS) LOADV(s + 1);
        COMPUTE(buf, (nt < 4) ? (h * 4 + nt) : (8 + h * 4 + nt - 4));
        if (s + 1 < NS) STOREV(buf ^ 1);
        __syncthreads();
    }

    /* epilogue: SwiGLU pairing warp-local (nt<4 = w1, nt>=4 = w3) */
    const int g = lane >> 2;
    const int cp = (lane & 3) * 2;
#pragma unroll
    for (int mt = 0; mt < 2; mt++) {
        const int r = pr0 + wm + mt * 16 + g;
#pragma unroll
        for (int j = 0; j < 4; j++) {
            const int col = n0 + h * 32 + j * 8 + cp;
            float a0 = acc[mt][j][0], a1 = acc[mt][j][1];
            float a2 = acc[mt][j][2], a3 = acc[mt][j][3];
            float g0 = acc[mt][j + 4][0], g1 = acc[mt][j + 4][1];
            float g2 = acc[mt][j + 4][2], g3 = acc[mt][j + 4][3];
            float s0 = (a0 / (1.f + __expf(-a0))) * g0;
            float s1 = (a1 / (1.f + __expf(-a1))) * g1;
            float s2 = (a2 / (1.f + __expf(-a2))) * g2;
            float s3 = (a3 / (1.f + __expf(-a3))) * g3;
            *(float2*)&g_hact[(size_t)r * FF + col] = make_float2(s0, s1);
            *(float2*)&g_hact[(size_t)(r + 8) * FF + col] = make_float2(s2, s3);
        }
    }
}

/* ------------------------------- GEMM2 -------------------------------
   g_y[row, n0..n0+127] = act @ w2^T.  NS = 8192/32 = 256.              */
__global__ __launch_bounds__(256)
void gemm2_k(const float* __restrict__ w2g) {
    extern __shared__ float smem[];
    const uint32_t sb = smem_u32(smem);
    const int tile = blockIdx.y;
    if (tile >= g_ntiles) return;
    const int e = g_tileE[tile];
    const int pr0 = g_tilePr0[tile];
    const int n0 = blockIdx.x * 128;

    const int tid = threadIdx.x;
    const int lane = tid & 31;
    const int w = tid >> 5;

    const int prow = tid >> 1;
    PRODUCER_SETUP(prow);
    const float* ap = g_hact + (size_t)(pr0 + prow) * FF + kh;
    const float* bp = w2g + ((size_t)e * HH + n0 + prow) * FF + kh;

    const int wm = (w & 3) * 32;
    const int h = w >> 2;
    const int tr0 = (w & 3) * 2;
    const int slotL = lane ^ ((lane >> 3) & 3);
    const uint32_t aoff = sb + slotL * 16;
    const uint32_t boff = sb + A_WORDS * 4 + slotL * 8;

    float acc[2][8][4];
#pragma unroll
    for (int m = 0; m < 2; m++)
#pragma unroll
        for (int n = 0; n < 8; n++)
#pragma unroll
            for (int i = 0; i < 4; i++) acc[m][n][i] = 0.f;

    float4 vA[4], vB[4];
    LOADV(0);
    STOREV(0);
    __syncthreads();

    const int NS = FF / 32;  /* 256 */
    for (int s = 0; s < NS; s++) {
        const int buf = s & 1;
        if (s + 1 < NS) LOADV(s + 1);
        COMPUTE(buf, h * 8 + nt);
        if (s + 1 < NS) STOREV(buf ^ 1);
        __syncthreads();
    }

    const int g = lane >> 2;
    const int cp = (lane & 3) * 2;
#pragma unroll
    for (int mt = 0; mt < 2; mt++) {
        const int r = pr0 + wm + mt * 16 + g;
#pragma unroll
        for (int nt = 0; nt < 8; nt++) {
            const int col = n0 + h * 64 + nt * 8 + cp;
            *(float2*)&g_y[(size_t)r * HH + col] =
                make_float2(acc[mt][nt][0], acc[mt][nt][1]);
            *(float2*)&g_y[(size_t)(r + 8) * HH + col] =
                make_float2(acc[mt][nt][2], acc[mt][nt][3]);
        }
    }
}

/* deterministic combine: out = w0*y[row0] + w1*y[row1] */
__global__ __launch_bounds__(256)
void combine_kernel(float* __restrict__ out) {
    int idx = blockIdx.x * blockDim.x + threadIdx.x;
    int t = idx >> 9;
    int h4 = (idx & 511) << 2;
    int r0 = g_trow[t * 2 + 0], r1 = g_trow[t * 2 + 1];
    float w0 = g_twt[t * 2 + 0], w1 = g_twt[t * 2 + 1];
    float4 y0 = *(const float4*)&g_y[(size_t)r0 * HH + h4];
    float4 y1 = *(const float4*)&g_y[(size_t)r1 * HH + h4];
    float4 o;
    o.x = w0 * y0.x + w1 * y1.x;
    o.y = w0 * y0.y + w1 * y1.y;
    o.z = w0 * y0.z + w1 * y1.z;
    o.w = w0 * y0.w + w1 * y1.w;
    *(float4*)&out[(size_t)t * HH + h4] = o;
}

/* ------------------------------ launch ------------------------------- */
extern "C" void kernel_launch(void* const* d_in, const int* in_sizes, int n_in,
                              void* d_out, int out_size) {
    const float* hs = (const float*)d_in[0];
    const float* gw = (const float*)d_in[1];
    const float* w1 = (const float*)d_in[2];
    const float* w2 = (const float*)d_in[3];
    const float* w3 = (const float*)d_in[4];
    float* out = (float*)d_out;

    cudaFuncSetAttribute(gemm1_k, cudaFuncAttributeMaxDynamicSharedMemorySize,
                         GEMM_SMEM);
    cudaFuncSetAttribute(gemm2_k, cudaFuncAttributeMaxDynamicSharedMemorySize,
                         GEMM_SMEM);

    zero_kernel<<<1, 32>>>();
    router_kernel<<<TT / 128, 128>>>(hs, gw);
    scan_kernel<<<1, 32>>>();
    build_kernel<<<TT / 256, 256>>>();
    {
        dim3 g(MAXTILES, FF / 64);               /* tiles fastest -> B L2 reuse */
        gemm1_k<<<g, 256, GEMM_SMEM>>>(hs, w1, w3);
    }
    {
        dim3 g(HH / 128, MAXTILES);              /* ncols fastest -> A L2 reuse */
        gemm2_k<<<g, 256, GEMM_SMEM>>>(w2);
    }
    combine_kernel<<<(TT * HH / 4) / 256, 256>>>(out);
}